// round 11
// baseline (speedup 1.0000x reference)
#include <cuda_runtime.h>
#include <cuda_bf16.h>
#include <cstdint>

// Problem dims
#define NN     16384
#define NFEAT  512
#define NHID   256
#define NH2    64
#define NCLASS 10
#define CAP    128   // max nnz per adj row (mean 32, binomial tail negligible)

#define GEMM1_BLOCKS 256          // (NN/128) * (NHID/128)
#define MEGA_GRID    (GEMM1_BLOCKS + NN)

// ---------------- device scratch (no allocation allowed) ----------------
__device__ float    d_XW1[NN * NHID];     // x @ W1            16 MB
__device__ float    d_HW2[NN * NH2];      // (relu(adj@XW1+b1)) @ W2   4 MB
__device__ int      d_cols[NN * CAP];     // ELL col indices    8 MB
__device__ float    d_vals[NN * CAP];     // ELL values         8 MB
__device__ int      d_cnt [NN];
__device__ unsigned d_gmax[NH2];          // encoded col-max
__device__ unsigned d_gemm_done;          // completed GEMM1 blocks

// monotonic float<->uint mapping for atomicMax over signed floats
__device__ __forceinline__ unsigned enc_f(float f) {
    unsigned s = __float_as_uint(f);
    return (s & 0x80000000u) ? ~s : (s | 0x80000000u);
}
__device__ __forceinline__ float dec_f(unsigned k) {
    return __uint_as_float((k & 0x80000000u) ? (k & 0x7fffffffu) : ~k);
}

// ---------------- mma / ldmatrix helpers ----------------
__device__ __forceinline__ uint32_t smem_u32(const void* p) {
    return (uint32_t)__cvta_generic_to_shared(p);
}
__device__ __forceinline__ void ldsm_x4(uint32_t* r, uint32_t addr) {
    asm volatile("ldmatrix.sync.aligned.m8n8.x4.shared.b16 {%0,%1,%2,%3}, [%4];"
                 : "=r"(r[0]), "=r"(r[1]), "=r"(r[2]), "=r"(r[3]) : "r"(addr));
}
__device__ __forceinline__ void ldsm_x4t(uint32_t* r, uint32_t addr) {
    asm volatile("ldmatrix.sync.aligned.m8n8.x4.trans.shared.b16 {%0,%1,%2,%3}, [%4];"
                 : "=r"(r[0]), "=r"(r[1]), "=r"(r[2]), "=r"(r[3]) : "r"(addr));
}
__device__ __forceinline__ void mma_bf16(float* c, const uint32_t* a, const uint32_t* b) {
    asm volatile("mma.sync.aligned.m16n8k16.row.col.f32.bf16.bf16.f32 "
                 "{%0,%1,%2,%3}, {%4,%5,%6,%7}, {%8,%9}, {%0,%1,%2,%3};"
                 : "+f"(c[0]), "+f"(c[1]), "+f"(c[2]), "+f"(c[3])
                 : "r"(a[0]), "r"(a[1]), "r"(a[2]), "r"(a[3]), "r"(b[0]), "r"(b[1]));
}
__device__ __forceinline__ void split_bf16(float v, __nv_bfloat16& hi, __nv_bfloat16& lo) {
    hi = __float2bfloat16(v);
    lo = __float2bfloat16(v - __bfloat162float(hi));
}

// shared-memory overlays for the two mega-kernel branches
struct GemmSmem {
    __nv_bfloat16 sAh[128][40];
    __nv_bfloat16 sAl[128][40];
    __nv_bfloat16 sBh[32][136];
    __nv_bfloat16 sBl[32][136];
};
struct ScanSmem {
    int   scol[CAP];
    float sval[CAP];
    float sh1 [NHID];
    float spart[4][NH2];
    int   scnt;
};

// ---------------- init ----------------
__global__ void init_state() {
    if (threadIdx.x < NH2) d_gmax[threadIdx.x] = 0u;   // smallest key under enc_f
    if (threadIdx.x == 0)  d_gemm_done = 0u;
}

// ---------------- MEGA: tc-GEMM1 (blocks 0..255) + scan->spmm1->gemm2 ----------
__global__ __launch_bounds__(256)
void mega(const float* __restrict__ x, const float* __restrict__ W1v,
          const float* __restrict__ adj, const float* __restrict__ b1,
          const float* __restrict__ W2v) {
    __shared__ __align__(16) char smem_raw[sizeof(GemmSmem)];
    const int tid = threadIdx.x;

    if (blockIdx.x < GEMM1_BLOCKS) {
        // ================= tensor-core GEMM1: XW1 = x @ W1 =================
        GemmSmem& S = *reinterpret_cast<GemmSmem*>(smem_raw);
        const int warp = tid >> 5, lane = tid & 31;
        const int wy = warp >> 1, wx = warp & 1;       // 4x2
        const int by = blockIdx.x >> 1, bx = blockIdx.x & 1;
        const int mBase = by * 128, nBase = bx * 128;

        float acc[2][8][4];
        #pragma unroll
        for (int mi = 0; mi < 2; mi++)
            #pragma unroll
            for (int ni = 0; ni < 8; ni++)
                #pragma unroll
                for (int e = 0; e < 4; e++) acc[mi][ni][e] = 0.f;

        const int aR = tid >> 3, aC = (tid & 7) * 4;     // A: 128x32
        const int bR = tid >> 5, bC = (tid & 31) * 4;    // B: 32x128

        for (int k0 = 0; k0 < NFEAT; k0 += 32) {
            #pragma unroll
            for (int it = 0; it < 4; it++) {
                const int r = aR + it * 32;
                float4 v = *(const float4*)(x + (size_t)(mBase + r) * NFEAT + k0 + aC);
                split_bf16(v.x, S.sAh[r][aC + 0], S.sAl[r][aC + 0]);
                split_bf16(v.y, S.sAh[r][aC + 1], S.sAl[r][aC + 1]);
                split_bf16(v.z, S.sAh[r][aC + 2], S.sAl[r][aC + 2]);
                split_bf16(v.w, S.sAh[r][aC + 3], S.sAl[r][aC + 3]);
            }
            #pragma unroll
            for (int it = 0; it < 4; it++) {
                const int r = bR + it * 8;
                float4 v = *(const float4*)(W1v + (size_t)(k0 + r) * NHID + nBase + bC);
                split_bf16(v.x, S.sBh[r][bC + 0], S.sBl[r][bC + 0]);
                split_bf16(v.y, S.sBh[r][bC + 1], S.sBl[r][bC + 1]);
                split_bf16(v.z, S.sBh[r][bC + 2], S.sBl[r][bC + 2]);
                split_bf16(v.w, S.sBh[r][bC + 3], S.sBl[r][bC + 3]);
            }
            __syncthreads();

            #pragma unroll
            for (int ks = 0; ks < 32; ks += 16) {
                uint32_t ah[2][4], al[2][4];
                const int arow = wy * 32 + (lane & 15);
                const int acol = ks + (lane >> 4) * 8;
                #pragma unroll
                for (int mi = 0; mi < 2; mi++) {
                    ldsm_x4(ah[mi], smem_u32(&S.sAh[arow + mi * 16][acol]));
                    ldsm_x4(al[mi], smem_u32(&S.sAl[arow + mi * 16][acol]));
                }
                uint32_t bh[8][2], bl[8][2];
                const int brow = ks + (lane & 15);
                #pragma unroll
                for (int np = 0; np < 4; np++) {
                    const int bcol = wx * 64 + np * 16 + (lane >> 4) * 8;
                    uint32_t t[4];
                    ldsm_x4t(t, smem_u32(&S.sBh[brow][bcol]));
                    bh[2*np][0] = t[0]; bh[2*np][1] = t[1];
                    bh[2*np+1][0] = t[2]; bh[2*np+1][1] = t[3];
                    ldsm_x4t(t, smem_u32(&S.sBl[brow][bcol]));
                    bl[2*np][0] = t[0]; bl[2*np][1] = t[1];
                    bl[2*np+1][0] = t[2]; bl[2*np+1][1] = t[3];
                }
                #pragma unroll
                for (int mi = 0; mi < 2; mi++)
                    #pragma unroll
                    for (int ni = 0; ni < 8; ni++) {
                        mma_bf16(acc[mi][ni], ah[mi], bh[ni]);  // hi*hi
                        mma_bf16(acc[mi][ni], ah[mi], bl[ni]);  // hi*lo
                        mma_bf16(acc[mi][ni], al[mi], bh[ni]);  // lo*hi
                    }
            }
            __syncthreads();
        }

        #pragma unroll
        for (int mi = 0; mi < 2; mi++) {
            const int row = mBase + wy * 32 + mi * 16 + (lane >> 2);
            #pragma unroll
            for (int ni = 0; ni < 8; ni++) {
                const int col = nBase + wx * 64 + ni * 8 + (lane & 3) * 2;
                *(float2*)(d_XW1 + (size_t)row * NHID + col) =
                    make_float2(acc[mi][ni][0], acc[mi][ni][1]);
                *(float2*)(d_XW1 + (size_t)(row + 8) * NHID + col) =
                    make_float2(acc[mi][ni][2], acc[mi][ni][3]);
            }
        }
        // publish: all stores visible, then count this block done
        __threadfence();
        __syncthreads();
        if (tid == 0) atomicAdd(&d_gemm_done, 1u);
    } else {
        // ========== scan row -> ELL -> (wait XW1) -> H1 row -> HW2 row ==========
        ScanSmem& S = *reinterpret_cast<ScanSmem*>(smem_raw);
        const int row = blockIdx.x - GEMM1_BLOCKS;
        if (tid == 0) S.scnt = 0;
        __syncthreads();

        // ---- scan: build ELL in smem, mirror to global (spmm2 needs it) ----
        const float4* arow = (const float4*)(adj + (size_t)row * NN);
        const int base = row * CAP;
        #pragma unroll 8
        for (int i = tid; i < NN / 4; i += 256) {
            float4 v = arow[i];
            if (v.x != 0.f) { int p = atomicAdd(&S.scnt, 1); if (p < CAP) { S.scol[p] = 4*i+0; S.sval[p] = v.x; d_cols[base+p] = 4*i+0; d_vals[base+p] = v.x; } }
            if (v.y != 0.f) { int p = atomicAdd(&S.scnt, 1); if (p < CAP) { S.scol[p] = 4*i+1; S.sval[p] = v.y; d_cols[base+p] = 4*i+1; d_vals[base+p] = v.y; } }
            if (v.z != 0.f) { int p = atomicAdd(&S.scnt, 1); if (p < CAP) { S.scol[p] = 4*i+2; S.sval[p] = v.z; d_cols[base+p] = 4*i+2; d_vals[base+p] = v.z; } }
            if (v.w != 0.f) { int p = atomicAdd(&S.scnt, 1); if (p < CAP) { S.scol[p] = 4*i+3; S.sval[p] = v.w; d_cols[base+p] = 4*i+3; d_vals[base+p] = v.w; } }
        }
        __syncthreads();
        const int n = min(S.scnt, CAP);
        if (tid == 0) d_cnt[row] = n;

        // ---- wait until GEMM1 fully published XW1 ----
        if (tid == 0) {
            while (atomicAdd(&d_gemm_done, 0u) < (unsigned)GEMM1_BLOCKS)
                __nanosleep(200);
            __threadfence();
        }
        __syncthreads();

        // ---- spmm1: H1[row][tid] = relu(b1[tid] + sum_i val*XW1[col][tid]) ----
        float acc = b1[tid];
        int i = 0;
        for (; i + 4 <= n; i += 4) {
            const float v0 = d_XW1[(size_t)S.scol[i]     * NHID + tid];
            const float v1 = d_XW1[(size_t)S.scol[i + 1] * NHID + tid];
            const float v2 = d_XW1[(size_t)S.scol[i + 2] * NHID + tid];
            const float v3 = d_XW1[(size_t)S.scol[i + 3] * NHID + tid];
            acc += S.sval[i] * v0 + S.sval[i + 1] * v1;
            acc += S.sval[i + 2] * v2 + S.sval[i + 3] * v3;
        }
        for (; i < n; i++)
            acc += S.sval[i] * d_XW1[(size_t)S.scol[i] * NHID + tid];
        S.sh1[tid] = fmaxf(acc, 0.f);
        __syncthreads();

        // ---- gemm2 epilogue: HW2[row][c] = sum_k sh1[k] * W2[k][c] ----
        const int c  = tid & 63;
        const int kq = tid >> 6;             // 0..3
        float s = 0.f;
        #pragma unroll 8
        for (int k = kq * 64; k < kq * 64 + 64; k++)
            s += S.sh1[k] * W2v[k * NH2 + c];
        S.spart[kq][c] = s;
        __syncthreads();
        if (tid < NH2)
            d_HW2[(size_t)row * NH2 + tid] =
                (S.spart[0][tid] + S.spart[1][tid]) + (S.spart[2][tid] + S.spart[3][tid]);
    }
}

// ---------------- SpMM2 + col-max: g = colmax(adj @ HW2 + b2) ----------------
// 16 rows per block; 16 lanes x float4; 8-deep unroll for MLP.
__global__ __launch_bounds__(256)
void spmm2_max(const float* __restrict__ b2) {
    const int r    = threadIdx.x >> 4;     // 0..15
    const int lane = threadIdx.x & 15;     // 0..15
    const int row  = blockIdx.x * 16 + r;

    __shared__ int   soff[16][CAP];
    __shared__ float sval[16][CAP];
    const int n = d_cnt[row];
    for (int i = lane; i < n; i += 16) {
        soff[r][i] = d_cols[row * CAP + i] * NH2;
        sval[r][i] = d_vals[row * CAP + i];
    }
    __syncthreads();

    float4 acc = *(const float4*)(b2 + lane * 4);
    int i = 0;
    for (; i + 8 <= n; i += 8) {
        float4 v[8];
        #pragma unroll
        for (int u = 0; u < 8; u++)
            v[u] = *(const float4*)(d_HW2 + soff[r][i + u] + lane * 4);
        #pragma unroll
        for (int u = 0; u < 8; u++) {
            const float s = sval[r][i + u];
            acc.x += s * v[u].x; acc.y += s * v[u].y;
            acc.z += s * v[u].z; acc.w += s * v[u].w;
        }
    }
    for (; i < n; i++) {
        const float4 v = *(const float4*)(d_HW2 + soff[r][i] + lane * 4);
        const float s = sval[r][i];
        acc.x += s * v.x; acc.y += s * v.y; acc.z += s * v.z; acc.w += s * v.w;
    }
    __syncthreads();
    __shared__ float4 smax[16][16];
    smax[r][lane] = acc;
    __syncthreads();
    if (r == 0) {
        float4 m = smax[0][lane];
        #pragma unroll
        for (int k = 1; k < 16; k++) {
            float4 v = smax[k][lane];
            m.x = fmaxf(m.x, v.x); m.y = fmaxf(m.y, v.y);
            m.z = fmaxf(m.z, v.z); m.w = fmaxf(m.w, v.w);
        }
        atomicMax(&d_gmax[lane * 4 + 0], enc_f(m.x));
        atomicMax(&d_gmax[lane * 4 + 1], enc_f(m.y));
        atomicMax(&d_gmax[lane * 4 + 2], enc_f(m.z));
        atomicMax(&d_gmax[lane * 4 + 3], enc_f(m.w));
    }
}

// ---------------- tiny MLP head: one block ----------------
__global__ void head(const float* __restrict__ W3, const float* __restrict__ b3,
                     const float* __restrict__ W4, const float* __restrict__ b4,
                     const float* __restrict__ W5, const float* __restrict__ b5,
                     float* __restrict__ out) {
    __shared__ float g[NH2], g3[32], g4[16];
    const int t = threadIdx.x;
    g[t] = dec_f(d_gmax[t]);
    __syncthreads();
    if (t < 32) {
        float a = b3[t];
        #pragma unroll
        for (int k = 0; k < NH2; k++) a += g[k] * W3[k * 32 + t];
        g3[t] = fmaxf(a, 0.f);
    }
    __syncthreads();
    if (t < 16) {
        float a = b4[t];
        #pragma unroll
        for (int k = 0; k < 32; k++) a += g3[k] * W4[k * 16 + t];
        g4[t] = fmaxf(a, 0.f);
    }
    __syncthreads();
    if (t < NCLASS) {
        float a = b5[t];
        #pragma unroll
        for (int k = 0; k < 16; k++) a += g4[k] * W5[k * NCLASS + t];
        out[t] = a;
    }
}

// ---------------- launch: ONLY kernel launches, fully graph-capturable ----------------
extern "C" void kernel_launch(void* const* d_in, const int* in_sizes, int n_in,
                              void* d_out, int out_size) {
    const float* x   = (const float*)d_in[0];
    const float* adj = (const float*)d_in[1];
    const float* W1  = (const float*)d_in[2];
    const float* b1  = (const float*)d_in[3];
    const float* W2  = (const float*)d_in[4];
    const float* b2  = (const float*)d_in[5];
    const float* W3  = (const float*)d_in[6];
    const float* b3  = (const float*)d_in[7];
    const float* W4  = (const float*)d_in[8];
    const float* b4  = (const float*)d_in[9];
    const float* W5  = (const float*)d_in[10];
    const float* b5  = (const float*)d_in[11];
    float* out = (float*)d_out;

    init_state<<<1, NH2>>>();
    mega<<<MEGA_GRID, 256>>>(x, W1, adj, b1, W2);
    spmm2_max<<<NN / 16, 256>>>(b2);
    head<<<1, NH2>>>(W3, b3, W4, b4, W5, b5, out);
}

// round 13
// speedup vs baseline: 1.2165x; 1.2165x over previous
#include <cuda_runtime.h>
#include <cuda_bf16.h>
#include <cstdint>

// Problem dims
#define NN     16384
#define NFEAT  512
#define NHID   256
#define NH2    64
#define NCLASS 10
#define CAP    128   // max nnz per adj row (mean 32, binomial tail negligible)

#define GEMM1_BLOCKS 256          // (NN/128) * (NHID/128)
#define SPMM2_GRID   (NN / 16)

// ---------------- device scratch (no allocation allowed) ----------------
__device__ float    d_XW1[NN * NHID];     // x @ W1            16 MB
__device__ float    d_HW2[NN * NH2];      // (relu(adj@XW1+b1)) @ W2   4 MB
__device__ int      d_cols[NN * CAP];     // ELL col indices    8 MB
__device__ float    d_vals[NN * CAP];     // ELL values         8 MB
__device__ int      d_cnt [NN];
__device__ unsigned d_gmax[NH2];          // encoded col-max
__device__ unsigned d_done;               // spmm2 block completion counter

// monotonic float<->uint mapping for atomicMax over signed floats
__device__ __forceinline__ unsigned enc_f(float f) {
    unsigned s = __float_as_uint(f);
    return (s & 0x80000000u) ? ~s : (s | 0x80000000u);
}
__device__ __forceinline__ float dec_f(unsigned k) {
    return __uint_as_float((k & 0x80000000u) ? (k & 0x7fffffffu) : ~k);
}

// ---------------- mma / ldmatrix helpers ----------------
__device__ __forceinline__ uint32_t smem_u32(const void* p) {
    return (uint32_t)__cvta_generic_to_shared(p);
}
__device__ __forceinline__ void ldsm_x4(uint32_t* r, uint32_t addr) {
    asm volatile("ldmatrix.sync.aligned.m8n8.x4.shared.b16 {%0,%1,%2,%3}, [%4];"
                 : "=r"(r[0]), "=r"(r[1]), "=r"(r[2]), "=r"(r[3]) : "r"(addr));
}
__device__ __forceinline__ void ldsm_x4t(uint32_t* r, uint32_t addr) {
    asm volatile("ldmatrix.sync.aligned.m8n8.x4.trans.shared.b16 {%0,%1,%2,%3}, [%4];"
                 : "=r"(r[0]), "=r"(r[1]), "=r"(r[2]), "=r"(r[3]) : "r"(addr));
}
__device__ __forceinline__ void mma_bf16(float* c, const uint32_t* a, const uint32_t* b) {
    asm volatile("mma.sync.aligned.m16n8k16.row.col.f32.bf16.bf16.f32 "
                 "{%0,%1,%2,%3}, {%4,%5,%6,%7}, {%8,%9}, {%0,%1,%2,%3};"
                 : "+f"(c[0]), "+f"(c[1]), "+f"(c[2]), "+f"(c[3])
                 : "r"(a[0]), "r"(a[1]), "r"(a[2]), "r"(a[3]), "r"(b[0]), "r"(b[1]));
}
__device__ __forceinline__ void split_bf16(float v, __nv_bfloat16& hi, __nv_bfloat16& lo) {
    hi = __float2bfloat16(v);
    lo = __float2bfloat16(v - __bfloat162float(hi));
}

// ---------------- GEMM1: XW1 = x @ W1, split-bf16 HMMA (+ init fold) ----------
__global__ __launch_bounds__(256)
void gemm1_tc(const float* __restrict__ x, const float* __restrict__ W1v) {
    // fold per-call state init into the first GEMM block (runs before spmm2)
    if (blockIdx.x == 0) {
        if (threadIdx.x < NH2) d_gmax[threadIdx.x] = 0u;
        if (threadIdx.x == 0)  d_done = 0u;
    }

    __shared__ __align__(16) __nv_bfloat16 sAh[128][40];
    __shared__ __align__(16) __nv_bfloat16 sAl[128][40];
    __shared__ __align__(16) __nv_bfloat16 sBh[32][136];
    __shared__ __align__(16) __nv_bfloat16 sBl[32][136];

    const int tid  = threadIdx.x;
    const int warp = tid >> 5, lane = tid & 31;
    const int wy = warp >> 1, wx = warp & 1;       // 4x2
    const int by = blockIdx.x >> 1, bx = blockIdx.x & 1;
    const int mBase = by * 128, nBase = bx * 128;

    float acc[2][8][4];
    #pragma unroll
    for (int mi = 0; mi < 2; mi++)
        #pragma unroll
        for (int ni = 0; ni < 8; ni++)
            #pragma unroll
            for (int e = 0; e < 4; e++) acc[mi][ni][e] = 0.f;

    const int aR = tid >> 3, aC = (tid & 7) * 4;     // A: 128x32
    const int bR = tid >> 5, bC = (tid & 31) * 4;    // B: 32x128

    for (int k0 = 0; k0 < NFEAT; k0 += 32) {
        #pragma unroll
        for (int it = 0; it < 4; it++) {
            const int r = aR + it * 32;
            float4 v = *(const float4*)(x + (size_t)(mBase + r) * NFEAT + k0 + aC);
            split_bf16(v.x, sAh[r][aC + 0], sAl[r][aC + 0]);
            split_bf16(v.y, sAh[r][aC + 1], sAl[r][aC + 1]);
            split_bf16(v.z, sAh[r][aC + 2], sAl[r][aC + 2]);
            split_bf16(v.w, sAh[r][aC + 3], sAl[r][aC + 3]);
        }
        #pragma unroll
        for (int it = 0; it < 4; it++) {
            const int r = bR + it * 8;
            float4 v = *(const float4*)(W1v + (size_t)(k0 + r) * NHID + nBase + bC);
            split_bf16(v.x, sBh[r][bC + 0], sBl[r][bC + 0]);
            split_bf16(v.y, sBh[r][bC + 1], sBl[r][bC + 1]);
            split_bf16(v.z, sBh[r][bC + 2], sBl[r][bC + 2]);
            split_bf16(v.w, sBh[r][bC + 3], sBl[r][bC + 3]);
        }
        __syncthreads();

        #pragma unroll
        for (int ks = 0; ks < 32; ks += 16) {
            uint32_t ah[2][4], al[2][4];
            const int arow = wy * 32 + (lane & 15);
            const int acol = ks + (lane >> 4) * 8;
            #pragma unroll
            for (int mi = 0; mi < 2; mi++) {
                ldsm_x4(ah[mi], smem_u32(&sAh[arow + mi * 16][acol]));
                ldsm_x4(al[mi], smem_u32(&sAl[arow + mi * 16][acol]));
            }
            uint32_t bh[8][2], bl[8][2];
            const int brow = ks + (lane & 15);
            #pragma unroll
            for (int np = 0; np < 4; np++) {
                const int bcol = wx * 64 + np * 16 + (lane >> 4) * 8;
                uint32_t t[4];
                ldsm_x4t(t, smem_u32(&sBh[brow][bcol]));
                bh[2*np][0] = t[0]; bh[2*np][1] = t[1];
                bh[2*np+1][0] = t[2]; bh[2*np+1][1] = t[3];
                ldsm_x4t(t, smem_u32(&sBl[brow][bcol]));
                bl[2*np][0] = t[0]; bl[2*np][1] = t[1];
                bl[2*np+1][0] = t[2]; bl[2*np+1][1] = t[3];
            }
            #pragma unroll
            for (int mi = 0; mi < 2; mi++)
                #pragma unroll
                for (int ni = 0; ni < 8; ni++) {
                    mma_bf16(acc[mi][ni], ah[mi], bh[ni]);  // hi*hi
                    mma_bf16(acc[mi][ni], ah[mi], bl[ni]);  // hi*lo
                    mma_bf16(acc[mi][ni], al[mi], bh[ni]);  // lo*hi
                }
        }
        __syncthreads();
    }

    #pragma unroll
    for (int mi = 0; mi < 2; mi++) {
        const int row = mBase + wy * 32 + mi * 16 + (lane >> 2);
        #pragma unroll
        for (int ni = 0; ni < 8; ni++) {
            const int col = nBase + wx * 64 + ni * 8 + (lane & 3) * 2;
            *(float2*)(d_XW1 + (size_t)row * NHID + col) =
                make_float2(acc[mi][ni][0], acc[mi][ni][1]);
            *(float2*)(d_XW1 + (size_t)(row + 8) * NHID + col) =
                make_float2(acc[mi][ni][2], acc[mi][ni][3]);
        }
    }
}

// ---------------- FUSED: scan row -> ELL -> H1 row -> HW2 row ----------------
__global__ __launch_bounds__(256)
void scan_spmm1_gemm2(const float* __restrict__ adj, const float* __restrict__ b1,
                      const float* __restrict__ W2v) {
    const int row = blockIdx.x;
    const int tid = threadIdx.x;

    __shared__ int   scnt;
    __shared__ int   scol[CAP];
    __shared__ float sval[CAP];
    __shared__ float sh1 [NHID];
    __shared__ float spart[4][NH2];

    if (tid == 0) scnt = 0;
    __syncthreads();

    // ---- scan: build ELL in smem, mirror to global (spmm2 needs it) ----
    const float4* arow = (const float4*)(adj + (size_t)row * NN);
    const int base = row * CAP;
    #pragma unroll 8
    for (int i = tid; i < NN / 4; i += 256) {
        float4 v = arow[i];
        if (v.x != 0.f) { int p = atomicAdd(&scnt, 1); if (p < CAP) { scol[p] = 4*i+0; sval[p] = v.x; d_cols[base+p] = 4*i+0; d_vals[base+p] = v.x; } }
        if (v.y != 0.f) { int p = atomicAdd(&scnt, 1); if (p < CAP) { scol[p] = 4*i+1; sval[p] = v.y; d_cols[base+p] = 4*i+1; d_vals[base+p] = v.y; } }
        if (v.z != 0.f) { int p = atomicAdd(&scnt, 1); if (p < CAP) { scol[p] = 4*i+2; sval[p] = v.z; d_cols[base+p] = 4*i+2; d_vals[base+p] = v.z; } }
        if (v.w != 0.f) { int p = atomicAdd(&scnt, 1); if (p < CAP) { scol[p] = 4*i+3; sval[p] = v.w; d_cols[base+p] = 4*i+3; d_vals[base+p] = v.w; } }
    }
    __syncthreads();
    const int n = min(scnt, CAP);
    if (tid == 0) d_cnt[row] = n;

    // ---- spmm1: H1[row][tid] = relu(b1[tid] + sum_i val*XW1[col][tid]) ----
    float acc = b1[tid];
    int i = 0;
    for (; i + 4 <= n; i += 4) {
        const float v0 = d_XW1[(size_t)scol[i]     * NHID + tid];
        const float v1 = d_XW1[(size_t)scol[i + 1] * NHID + tid];
        const float v2 = d_XW1[(size_t)scol[i + 2] * NHID + tid];
        const float v3 = d_XW1[(size_t)scol[i + 3] * NHID + tid];
        acc += sval[i] * v0 + sval[i + 1] * v1;
        acc += sval[i + 2] * v2 + sval[i + 3] * v3;
    }
    for (; i < n; i++)
        acc += sval[i] * d_XW1[(size_t)scol[i] * NHID + tid];
    sh1[tid] = fmaxf(acc, 0.f);
    __syncthreads();

    // ---- gemm2 epilogue: HW2[row][c] = sum_k sh1[k] * W2[k][c] ----
    const int c  = tid & 63;
    const int kq = tid >> 6;             // 0..3
    float s = 0.f;
    #pragma unroll 8
    for (int k = kq * 64; k < kq * 64 + 64; k++)
        s += sh1[k] * W2v[k * NH2 + c];
    spart[kq][c] = s;
    __syncthreads();
    if (tid < NH2)
        d_HW2[(size_t)row * NH2 + tid] =
            (spart[0][tid] + spart[1][tid]) + (spart[2][tid] + spart[3][tid]);
}

// ---------------- SpMM2 + col-max + fused head (last block) ----------------
// 16 rows per block; 16 lanes x float4; 8-deep unroll for MLP.
__global__ __launch_bounds__(256)
void spmm2_max_head(const float* __restrict__ b2,
                    const float* __restrict__ W3, const float* __restrict__ b3,
                    const float* __restrict__ W4, const float* __restrict__ b4,
                    const float* __restrict__ W5, const float* __restrict__ b5,
                    float* __restrict__ out) {
    const int r    = threadIdx.x >> 4;     // 0..15
    const int lane = threadIdx.x & 15;     // 0..15
    const int row  = blockIdx.x * 16 + r;

    __shared__ int   soff[16][CAP];
    __shared__ float sval[16][CAP];
    const int n = d_cnt[row];
    for (int i = lane; i < n; i += 16) {
        soff[r][i] = d_cols[row * CAP + i] * NH2;
        sval[r][i] = d_vals[row * CAP + i];
    }
    __syncthreads();

    float4 acc = *(const float4*)(b2 + lane * 4);
    int i = 0;
    for (; i + 8 <= n; i += 8) {
        float4 v[8];
        #pragma unroll
        for (int u = 0; u < 8; u++)
            v[u] = *(const float4*)(d_HW2 + soff[r][i + u] + lane * 4);
        #pragma unroll
        for (int u = 0; u < 8; u++) {
            const float s = sval[r][i + u];
            acc.x += s * v[u].x; acc.y += s * v[u].y;
            acc.z += s * v[u].z; acc.w += s * v[u].w;
        }
    }
    for (; i < n; i++) {
        const float4 v = *(const float4*)(d_HW2 + soff[r][i] + lane * 4);
        const float s = sval[r][i];
        acc.x += s * v.x; acc.y += s * v.y; acc.z += s * v.z; acc.w += s * v.w;
    }
    __syncthreads();
    __shared__ float4 smax[16][16];
    smax[r][lane] = acc;
    __syncthreads();
    if (r == 0) {
        float4 m = smax[0][lane];
        #pragma unroll
        for (int k = 1; k < 16; k++) {
            float4 v = smax[k][lane];
            m.x = fmaxf(m.x, v.x); m.y = fmaxf(m.y, v.y);
            m.z = fmaxf(m.z, v.z); m.w = fmaxf(m.w, v.w);
        }
        atomicMax(&d_gmax[lane * 4 + 0], enc_f(m.x));
        atomicMax(&d_gmax[lane * 4 + 1], enc_f(m.y));
        atomicMax(&d_gmax[lane * 4 + 2], enc_f(m.z));
        atomicMax(&d_gmax[lane * 4 + 3], enc_f(m.w));
    }

    // ---- last-block head: g -> W3 -> W4 -> W5 -> out ----
    __threadfence();
    __syncthreads();
    __shared__ unsigned isLast;
    if (threadIdx.x == 0)
        isLast = (atomicAdd(&d_done, 1u) == (unsigned)(SPMM2_GRID - 1)) ? 1u : 0u;
    __syncthreads();
    if (!isLast) return;
    __threadfence();  // acquire: see all other blocks' gmax updates

    __shared__ float g[NH2], g3[32], g4[16];
    const int t = threadIdx.x;
    if (t < NH2) g[t] = dec_f(d_gmax[t]);
    __syncthreads();
    if (t < 32) {
        float a = b3[t];
        #pragma unroll
        for (int k = 0; k < NH2; k++) a += g[k] * W3[k * 32 + t];
        g3[t] = fmaxf(a, 0.f);
    }
    __syncthreads();
    if (t < 16) {
        float a = b4[t];
        #pragma unroll
        for (int k = 0; k < 32; k++) a += g3[k] * W4[k * 16 + t];
        g4[t] = fmaxf(a, 0.f);
    }
    __syncthreads();
    if (t < NCLASS) {
        float a = b5[t];
        #pragma unroll
        for (int k = 0; k < 16; k++) a += g4[k] * W5[k * NCLASS + t];
        out[t] = a;
    }
}

// ---------------- launch: ONLY kernel launches, fully graph-capturable ----------------
extern "C" void kernel_launch(void* const* d_in, const int* in_sizes, int n_in,
                              void* d_out, int out_size) {
    const float* x   = (const float*)d_in[0];
    const float* adj = (const float*)d_in[1];
    const float* W1  = (const float*)d_in[2];
    const float* b1  = (const float*)d_in[3];
    const float* W2  = (const float*)d_in[4];
    const float* b2  = (const float*)d_in[5];
    const float* W3  = (const float*)d_in[6];
    const float* b3  = (const float*)d_in[7];
    const float* W4  = (const float*)d_in[8];
    const float* b4  = (const float*)d_in[9];
    const float* W5  = (const float*)d_in[10];
    const float* b5  = (const float*)d_in[11];
    float* out = (float*)d_out;

    gemm1_tc<<<GEMM1_BLOCKS, 256>>>(x, W1);
    scan_spmm1_gemm2<<<NN, 256>>>(adj, b1, W2);
    spmm2_max_head<<<SPMM2_GRID, 256>>>(b2, W3, b3, W4, b4, W5, b5, out);
}

// round 14
// speedup vs baseline: 1.5597x; 1.2821x over previous
#include <cuda_runtime.h>
#include <cuda_bf16.h>
#include <cstdint>

// Problem dims
#define NN     16384
#define NFEAT  512
#define NHID   256
#define NH2    64
#define NCLASS 10
#define CAP    128   // max nnz per adj row (mean 32, binomial tail negligible)

#define GEMM1_BLOCKS 512          // (NN/64) * (NHID/128)

// ---------------- device scratch (no allocation allowed) ----------------
__device__ float    d_XW1[NN * NHID];     // x @ W1            16 MB
__device__ float    d_HW2[NN * NH2];      // (relu(adj@XW1+b1)) @ W2   4 MB
__device__ int      d_cols[NN * CAP];     // ELL col indices    8 MB
__device__ float    d_vals[NN * CAP];     // ELL values         8 MB
__device__ int      d_cnt [NN];
__device__ unsigned d_gmax[NH2];          // encoded col-max

// monotonic float<->uint mapping for atomicMax over signed floats
__device__ __forceinline__ unsigned enc_f(float f) {
    unsigned s = __float_as_uint(f);
    return (s & 0x80000000u) ? ~s : (s | 0x80000000u);
}
__device__ __forceinline__ float dec_f(unsigned k) {
    return __uint_as_float((k & 0x80000000u) ? (k & 0x7fffffffu) : ~k);
}

// ---------------- mma / ldmatrix helpers ----------------
__device__ __forceinline__ uint32_t smem_u32(const void* p) {
    return (uint32_t)__cvta_generic_to_shared(p);
}
__device__ __forceinline__ void ldsm_x4(uint32_t* r, uint32_t addr) {
    asm volatile("ldmatrix.sync.aligned.m8n8.x4.shared.b16 {%0,%1,%2,%3}, [%4];"
                 : "=r"(r[0]), "=r"(r[1]), "=r"(r[2]), "=r"(r[3]) : "r"(addr));
}
__device__ __forceinline__ void ldsm_x4t(uint32_t* r, uint32_t addr) {
    asm volatile("ldmatrix.sync.aligned.m8n8.x4.trans.shared.b16 {%0,%1,%2,%3}, [%4];"
                 : "=r"(r[0]), "=r"(r[1]), "=r"(r[2]), "=r"(r[3]) : "r"(addr));
}
__device__ __forceinline__ void mma_bf16(float* c, const uint32_t* a, const uint32_t* b) {
    asm volatile("mma.sync.aligned.m16n8k16.row.col.f32.bf16.bf16.f32 "
                 "{%0,%1,%2,%3}, {%4,%5,%6,%7}, {%8,%9}, {%0,%1,%2,%3};"
                 : "+f"(c[0]), "+f"(c[1]), "+f"(c[2]), "+f"(c[3])
                 : "r"(a[0]), "r"(a[1]), "r"(a[2]), "r"(a[3]), "r"(b[0]), "r"(b[1]));
}
__device__ __forceinline__ void split_bf16(float v, __nv_bfloat16& hi, __nv_bfloat16& lo) {
    hi = __float2bfloat16(v);
    lo = __float2bfloat16(v - __bfloat162float(hi));
}

// ---------------- init ----------------
__global__ void init_gmax() {
    d_gmax[threadIdx.x] = 0u;  // smallest key under enc_f
}

// ---------------- GEMM1: XW1 = x @ W1, split-bf16 HMMA ----------------
// BM=64, BN=128, BK=32; 8 warps 2x4; warp tile 32x32; 3-term split, fp32 acc.
// 512 blocks -> 3.5 waves on 148 SMs (vs 1.7 for 128x128): better balance,
// acc regs halved -> higher occupancy.
__global__ __launch_bounds__(256)
void gemm1_tc(const float* __restrict__ x, const float* __restrict__ W1v) {
    __shared__ __align__(16) __nv_bfloat16 sAh[64][40];
    __shared__ __align__(16) __nv_bfloat16 sAl[64][40];
    __shared__ __align__(16) __nv_bfloat16 sBh[32][136];
    __shared__ __align__(16) __nv_bfloat16 sBl[32][136];

    const int tid  = threadIdx.x;
    const int warp = tid >> 5, lane = tid & 31;
    const int wy = warp >> 2, wx = warp & 3;       // 2x4
    const int by = blockIdx.x >> 1, bx = blockIdx.x & 1;
    const int mBase = by * 64, nBase = bx * 128;

    float acc[2][4][4];
    #pragma unroll
    for (int mi = 0; mi < 2; mi++)
        #pragma unroll
        for (int ni = 0; ni < 4; ni++)
            #pragma unroll
            for (int e = 0; e < 4; e++) acc[mi][ni][e] = 0.f;

    const int aR = tid >> 3, aC = (tid & 7) * 4;     // A: 64x32, 32 rows/pass
    const int bR = tid >> 5, bC = (tid & 31) * 4;    // B: 32x128, 8 rows/pass

    for (int k0 = 0; k0 < NFEAT; k0 += 32) {
        #pragma unroll
        for (int it = 0; it < 2; it++) {
            const int r = aR + it * 32;
            float4 v = *(const float4*)(x + (size_t)(mBase + r) * NFEAT + k0 + aC);
            split_bf16(v.x, sAh[r][aC + 0], sAl[r][aC + 0]);
            split_bf16(v.y, sAh[r][aC + 1], sAl[r][aC + 1]);
            split_bf16(v.z, sAh[r][aC + 2], sAl[r][aC + 2]);
            split_bf16(v.w, sAh[r][aC + 3], sAl[r][aC + 3]);
        }
        #pragma unroll
        for (int it = 0; it < 4; it++) {
            const int r = bR + it * 8;
            float4 v = *(const float4*)(W1v + (size_t)(k0 + r) * NHID + nBase + bC);
            split_bf16(v.x, sBh[r][bC + 0], sBl[r][bC + 0]);
            split_bf16(v.y, sBh[r][bC + 1], sBl[r][bC + 1]);
            split_bf16(v.z, sBh[r][bC + 2], sBl[r][bC + 2]);
            split_bf16(v.w, sBh[r][bC + 3], sBl[r][bC + 3]);
        }
        __syncthreads();

        #pragma unroll
        for (int ks = 0; ks < 32; ks += 16) {
            // A fragments: warp spans rows [wy*32, wy*32+32)
            uint32_t ah[2][4], al[2][4];
            const int arow = wy * 32 + (lane & 15);
            const int acol = ks + (lane >> 4) * 8;
            #pragma unroll
            for (int mi = 0; mi < 2; mi++) {
                ldsm_x4(ah[mi], smem_u32(&sAh[arow + mi * 16][acol]));
                ldsm_x4(al[mi], smem_u32(&sAl[arow + mi * 16][acol]));
            }
            // B fragments: warp spans cols [wx*32, wx*32+32); 2 n-tile pairs
            uint32_t bh[4][2], bl[4][2];
            const int brow = ks + (lane & 15);
            #pragma unroll
            for (int np = 0; np < 2; np++) {
                const int bcol = wx * 32 + np * 16 + (lane >> 4) * 8;
                uint32_t t[4];
                ldsm_x4t(t, smem_u32(&sBh[brow][bcol]));
                bh[2*np][0] = t[0]; bh[2*np][1] = t[1];
                bh[2*np+1][0] = t[2]; bh[2*np+1][1] = t[3];
                ldsm_x4t(t, smem_u32(&sBl[brow][bcol]));
                bl[2*np][0] = t[0]; bl[2*np][1] = t[1];
                bl[2*np+1][0] = t[2]; bl[2*np+1][1] = t[3];
            }
            #pragma unroll
            for (int mi = 0; mi < 2; mi++)
                #pragma unroll
                for (int ni = 0; ni < 4; ni++) {
                    mma_bf16(acc[mi][ni], ah[mi], bh[ni]);  // hi*hi
                    mma_bf16(acc[mi][ni], ah[mi], bl[ni]);  // hi*lo
                    mma_bf16(acc[mi][ni], al[mi], bh[ni]);  // lo*hi
                }
        }
        __syncthreads();
    }

    #pragma unroll
    for (int mi = 0; mi < 2; mi++) {
        const int row = mBase + wy * 32 + mi * 16 + (lane >> 2);
        #pragma unroll
        for (int ni = 0; ni < 4; ni++) {
            const int col = nBase + wx * 32 + ni * 8 + (lane & 3) * 2;
            *(float2*)(d_XW1 + (size_t)row * NHID + col) =
                make_float2(acc[mi][ni][0], acc[mi][ni][1]);
            *(float2*)(d_XW1 + (size_t)(row + 8) * NHID + col) =
                make_float2(acc[mi][ni][2], acc[mi][ni][3]);
        }
    }
}

// ---------------- FUSED: scan row -> ELL -> H1 row -> HW2 row (R10 verbatim) ----
__global__ __launch_bounds__(256)
void scan_spmm1_gemm2(const float* __restrict__ adj, const float* __restrict__ b1,
                      const float* __restrict__ W2v) {
    const int row = blockIdx.x;
    const int tid = threadIdx.x;

    __shared__ int   scnt;
    __shared__ int   scol[CAP];
    __shared__ float sval[CAP];
    __shared__ float sh1 [NHID];
    __shared__ float spart[4][NH2];

    if (tid == 0) scnt = 0;
    __syncthreads();

    // ---- scan: build ELL in smem, mirror to global (spmm2 needs it) ----
    const float4* arow = (const float4*)(adj + (size_t)row * NN);
    const int base = row * CAP;
    #pragma unroll 8
    for (int i = tid; i < NN / 4; i += 256) {
        float4 v = arow[i];
        if (v.x != 0.f) { int p = atomicAdd(&scnt, 1); if (p < CAP) { scol[p] = 4*i+0; sval[p] = v.x; d_cols[base+p] = 4*i+0; d_vals[base+p] = v.x; } }
        if (v.y != 0.f) { int p = atomicAdd(&scnt, 1); if (p < CAP) { scol[p] = 4*i+1; sval[p] = v.y; d_cols[base+p] = 4*i+1; d_vals[base+p] = v.y; } }
        if (v.z != 0.f) { int p = atomicAdd(&scnt, 1); if (p < CAP) { scol[p] = 4*i+2; sval[p] = v.z; d_cols[base+p] = 4*i+2; d_vals[base+p] = v.z; } }
        if (v.w != 0.f) { int p = atomicAdd(&scnt, 1); if (p < CAP) { scol[p] = 4*i+3; sval[p] = v.w; d_cols[base+p] = 4*i+3; d_vals[base+p] = v.w; } }
    }
    __syncthreads();
    const int n = min(scnt, CAP);
    if (tid == 0) d_cnt[row] = n;

    // ---- spmm1: H1[row][tid] = relu(b1[tid] + sum_i val*XW1[col][tid]) ----
    float acc = b1[tid];
    int i = 0;
    for (; i + 4 <= n; i += 4) {
        const float v0 = d_XW1[(size_t)scol[i]     * NHID + tid];
        const float v1 = d_XW1[(size_t)scol[i + 1] * NHID + tid];
        const float v2 = d_XW1[(size_t)scol[i + 2] * NHID + tid];
        const float v3 = d_XW1[(size_t)scol[i + 3] * NHID + tid];
        acc += sval[i] * v0 + sval[i + 1] * v1;
        acc += sval[i + 2] * v2 + sval[i + 3] * v3;
    }
    for (; i < n; i++)
        acc += sval[i] * d_XW1[(size_t)scol[i] * NHID + tid];
    sh1[tid] = fmaxf(acc, 0.f);
    __syncthreads();

    // ---- gemm2 epilogue: HW2[row][c] = sum_k sh1[k] * W2[k][c] ----
    const int c  = tid & 63;
    const int kq = tid >> 6;             // 0..3
    float s = 0.f;
    #pragma unroll 8
    for (int k = kq * 64; k < kq * 64 + 64; k++)
        s += sh1[k] * W2v[k * NH2 + c];
    spart[kq][c] = s;
    __syncthreads();
    if (tid < NH2)
        d_HW2[(size_t)row * NH2 + tid] =
            (spart[0][tid] + spart[1][tid]) + (spart[2][tid] + spart[3][tid]);
}

// ---------------- SpMM2 + col-max (R10 verbatim, MLP-4) ----------------
__global__ __launch_bounds__(256)
void spmm2_max(const float* __restrict__ b2) {
    const int r    = threadIdx.x >> 4;     // 0..15
    const int lane = threadIdx.x & 15;     // 0..15
    const int row  = blockIdx.x * 16 + r;

    __shared__ int   soff[16][CAP];
    __shared__ float sval[16][CAP];
    const int n = d_cnt[row];
    for (int i = lane; i < n; i += 16) {
        soff[r][i] = d_cols[row * CAP + i] * NH2;
        sval[r][i] = d_vals[row * CAP + i];
    }
    __syncthreads();

    float4 acc = *(const float4*)(b2 + lane * 4);
    int i = 0;
    for (; i + 4 <= n; i += 4) {
        const float4 v0 = *(const float4*)(d_HW2 + soff[r][i]     + lane * 4);
        const float4 v1 = *(const float4*)(d_HW2 + soff[r][i + 1] + lane * 4);
        const float4 v2 = *(const float4*)(d_HW2 + soff[r][i + 2] + lane * 4);
        const float4 v3 = *(const float4*)(d_HW2 + soff[r][i + 3] + lane * 4);
        const float s0 = sval[r][i], s1 = sval[r][i+1], s2 = sval[r][i+2], s3 = sval[r][i+3];
        acc.x += s0 * v0.x; acc.y += s0 * v0.y; acc.z += s0 * v0.z; acc.w += s0 * v0.w;
        acc.x += s1 * v1.x; acc.y += s1 * v1.y; acc.z += s1 * v1.z; acc.w += s1 * v1.w;
        acc.x += s2 * v2.x; acc.y += s2 * v2.y; acc.z += s2 * v2.z; acc.w += s2 * v2.w;
        acc.x += s3 * v3.x; acc.y += s3 * v3.y; acc.z += s3 * v3.z; acc.w += s3 * v3.w;
    }
    for (; i < n; i++) {
        const float4 v = *(const float4*)(d_HW2 + soff[r][i] + lane * 4);
        const float s = sval[r][i];
        acc.x += s * v.x; acc.y += s * v.y; acc.z += s * v.z; acc.w += s * v.w;
    }
    __syncthreads();
    __shared__ float4 smax[16][16];
    smax[r][lane] = acc;
    __syncthreads();
    if (r == 0) {
        float4 m = smax[0][lane];
        #pragma unroll
        for (int k = 1; k < 16; k++) {
            float4 v = smax[k][lane];
            m.x = fmaxf(m.x, v.x); m.y = fmaxf(m.y, v.y);
            m.z = fmaxf(m.z, v.z); m.w = fmaxf(m.w, v.w);
        }
        atomicMax(&d_gmax[lane * 4 + 0], enc_f(m.x));
        atomicMax(&d_gmax[lane * 4 + 1], enc_f(m.y));
        atomicMax(&d_gmax[lane * 4 + 2], enc_f(m.z));
        atomicMax(&d_gmax[lane * 4 + 3], enc_f(m.w));
    }
}

// ---------------- tiny MLP head: one block (R10 verbatim) ----------------
__global__ void head(const float* __restrict__ W3, const float* __restrict__ b3,
                     const float* __restrict__ W4, const float* __restrict__ b4,
                     const float* __restrict__ W5, const float* __restrict__ b5,
                     float* __restrict__ out) {
    __shared__ float g[NH2], g3[32], g4[16];
    const int t = threadIdx.x;
    g[t] = dec_f(d_gmax[t]);
    __syncthreads();
    if (t < 32) {
        float a = b3[t];
        #pragma unroll
        for (int k = 0; k < NH2; k++) a += g[k] * W3[k * 32 + t];
        g3[t] = fmaxf(a, 0.f);
    }
    __syncthreads();
    if (t < 16) {
        float a = b4[t];
        #pragma unroll
        for (int k = 0; k < 32; k++) a += g3[k] * W4[k * 16 + t];
        g4[t] = fmaxf(a, 0.f);
    }
    __syncthreads();
    if (t < NCLASS) {
        float a = b5[t];
        #pragma unroll
        for (int k = 0; k < 16; k++) a += g4[k] * W5[k * NCLASS + t];
        out[t] = a;
    }
}

// ---------------- launch: ONLY kernel launches, fully graph-capturable ----------------
extern "C" void kernel_launch(void* const* d_in, const int* in_sizes, int n_in,
                              void* d_out, int out_size) {
    const float* x   = (const float*)d_in[0];
    const float* adj = (const float*)d_in[1];
    const float* W1  = (const float*)d_in[2];
    const float* b1  = (const float*)d_in[3];
    const float* W2  = (const float*)d_in[4];
    const float* b2  = (const float*)d_in[5];
    const float* W3  = (const float*)d_in[6];
    const float* b3  = (const float*)d_in[7];
    const float* W4  = (const float*)d_in[8];
    const float* b4  = (const float*)d_in[9];
    const float* W5  = (const float*)d_in[10];
    const float* b5  = (const float*)d_in[11];
    float* out = (float*)d_out;

    init_gmax<<<1, NH2>>>();
    gemm1_tc<<<GEMM1_BLOCKS, 256>>>(x, W1);
    scan_spmm1_gemm2<<<NN, 256>>>(adj, b1, W2);
    spmm2_max<<<NN / 16, 256>>>(b2);
    head<<<1, NH2>>>(W3, b3, W4, b4, W5, b5, out);
}

// round 17
// speedup vs baseline: 1.6912x; 1.0843x over previous
#include <cuda_runtime.h>
#include <cuda_bf16.h>
#include <cuda_fp16.h>
#include <cstdint>

// Problem dims
#define NN     16384
#define NFEAT  512
#define NHID   256
#define NH2    64
#define NCLASS 10
#define CAP    128   // max nnz per adj row (mean 32, binomial tail negligible)

#define GEMM1_BLOCKS 256          // (NN/128) * (NHID/128)

// ---------------- device scratch (no allocation allowed) ----------------
__device__ __half   d_XW1h[NN * NHID];    // x @ W1 in fp16     8 MB (halves gather traffic)
__device__ float    d_HW2[NN * NH2];      // (relu(adj@XW1+b1)) @ W2   4 MB
__device__ int      d_cols[NN * CAP];     // ELL col indices    8 MB
__device__ float    d_vals[NN * CAP];     // ELL values         8 MB
__device__ int      d_cnt [NN];
__device__ unsigned d_gmax[NH2];          // encoded col-max

// monotonic float<->uint mapping for atomicMax over signed floats
__device__ __forceinline__ unsigned enc_f(float f) {
    unsigned s = __float_as_uint(f);
    return (s & 0x80000000u) ? ~s : (s | 0x80000000u);
}
__device__ __forceinline__ float dec_f(unsigned k) {
    return __uint_as_float((k & 0x80000000u) ? (k & 0x7fffffffu) : ~k);
}

// ---------------- mma / ldmatrix helpers ----------------
__device__ __forceinline__ uint32_t smem_u32(const void* p) {
    return (uint32_t)__cvta_generic_to_shared(p);
}
__device__ __forceinline__ void ldsm_x4(uint32_t* r, uint32_t addr) {
    asm volatile("ldmatrix.sync.aligned.m8n8.x4.shared.b16 {%0,%1,%2,%3}, [%4];"
                 : "=r"(r[0]), "=r"(r[1]), "=r"(r[2]), "=r"(r[3]) : "r"(addr));
}
__device__ __forceinline__ void ldsm_x4t(uint32_t* r, uint32_t addr) {
    asm volatile("ldmatrix.sync.aligned.m8n8.x4.trans.shared.b16 {%0,%1,%2,%3}, [%4];"
                 : "=r"(r[0]), "=r"(r[1]), "=r"(r[2]), "=r"(r[3]) : "r"(addr));
}
__device__ __forceinline__ void mma_bf16(float* c, const uint32_t* a, const uint32_t* b) {
    asm volatile("mma.sync.aligned.m16n8k16.row.col.f32.bf16.bf16.f32 "
                 "{%0,%1,%2,%3}, {%4,%5,%6,%7}, {%8,%9}, {%0,%1,%2,%3};"
                 : "+f"(c[0]), "+f"(c[1]), "+f"(c[2]), "+f"(c[3])
                 : "r"(a[0]), "r"(a[1]), "r"(a[2]), "r"(a[3]), "r"(b[0]), "r"(b[1]));
}
__device__ __forceinline__ void split_bf16(float v, __nv_bfloat16& hi, __nv_bfloat16& lo) {
    hi = __float2bfloat16(v);
    lo = __float2bfloat16(v - __bfloat162float(hi));
}

// ---------------- init ----------------
__global__ void init_gmax() {
    d_gmax[threadIdx.x] = 0u;  // smallest key under enc_f
}

// ---------------- GEMM1: XW1 = x @ W1, split-bf16 HMMA (128x128 tile) ----------
// fp32 accumulate; epilogue rounds to fp16 (eps ~2.4e-4) to halve gather bytes.
__global__ __launch_bounds__(256)
void gemm1_tc(const float* __restrict__ x, const float* __restrict__ W1v) {
    __shared__ __align__(16) __nv_bfloat16 sAh[128][40];
    __shared__ __align__(16) __nv_bfloat16 sAl[128][40];
    __shared__ __align__(16) __nv_bfloat16 sBh[32][136];
    __shared__ __align__(16) __nv_bfloat16 sBl[32][136];

    const int tid  = threadIdx.x;
    const int warp = tid >> 5, lane = tid & 31;
    const int wy = warp >> 1, wx = warp & 1;       // 4x2
    const int by = blockIdx.x >> 1, bx = blockIdx.x & 1;
    const int mBase = by * 128, nBase = bx * 128;

    float acc[2][8][4];
    #pragma unroll
    for (int mi = 0; mi < 2; mi++)
        #pragma unroll
        for (int ni = 0; ni < 8; ni++)
            #pragma unroll
            for (int e = 0; e < 4; e++) acc[mi][ni][e] = 0.f;

    const int aR = tid >> 3, aC = (tid & 7) * 4;     // A: 128x32
    const int bR = tid >> 5, bC = (tid & 31) * 4;    // B: 32x128

    for (int k0 = 0; k0 < NFEAT; k0 += 32) {
        #pragma unroll
        for (int it = 0; it < 4; it++) {
            const int r = aR + it * 32;
            float4 v = *(const float4*)(x + (size_t)(mBase + r) * NFEAT + k0 + aC);
            split_bf16(v.x, sAh[r][aC + 0], sAl[r][aC + 0]);
            split_bf16(v.y, sAh[r][aC + 1], sAl[r][aC + 1]);
            split_bf16(v.z, sAh[r][aC + 2], sAl[r][aC + 2]);
            split_bf16(v.w, sAh[r][aC + 3], sAl[r][aC + 3]);
        }
        #pragma unroll
        for (int it = 0; it < 4; it++) {
            const int r = bR + it * 8;
            float4 v = *(const float4*)(W1v + (size_t)(k0 + r) * NHID + nBase + bC);
            split_bf16(v.x, sBh[r][bC + 0], sBl[r][bC + 0]);
            split_bf16(v.y, sBh[r][bC + 1], sBl[r][bC + 1]);
            split_bf16(v.z, sBh[r][bC + 2], sBl[r][bC + 2]);
            split_bf16(v.w, sBh[r][bC + 3], sBl[r][bC + 3]);
        }
        __syncthreads();

        #pragma unroll
        for (int ks = 0; ks < 32; ks += 16) {
            uint32_t ah[2][4], al[2][4];
            const int arow = wy * 32 + (lane & 15);
            const int acol = ks + (lane >> 4) * 8;
            #pragma unroll
            for (int mi = 0; mi < 2; mi++) {
                ldsm_x4(ah[mi], smem_u32(&sAh[arow + mi * 16][acol]));
                ldsm_x4(al[mi], smem_u32(&sAl[arow + mi * 16][acol]));
            }
            uint32_t bh[8][2], bl[8][2];
            const int brow = ks + (lane & 15);
            #pragma unroll
            for (int np = 0; np < 4; np++) {
                const int bcol = wx * 64 + np * 16 + (lane >> 4) * 8;
                uint32_t t[4];
                ldsm_x4t(t, smem_u32(&sBh[brow][bcol]));
                bh[2*np][0] = t[0]; bh[2*np][1] = t[1];
                bh[2*np+1][0] = t[2]; bh[2*np+1][1] = t[3];
                ldsm_x4t(t, smem_u32(&sBl[brow][bcol]));
                bl[2*np][0] = t[0]; bl[2*np][1] = t[1];
                bl[2*np+1][0] = t[2]; bl[2*np+1][1] = t[3];
            }
            #pragma unroll
            for (int mi = 0; mi < 2; mi++)
                #pragma unroll
                for (int ni = 0; ni < 8; ni++) {
                    mma_bf16(acc[mi][ni], ah[mi], bh[ni]);  // hi*hi
                    mma_bf16(acc[mi][ni], ah[mi], bl[ni]);  // hi*lo
                    mma_bf16(acc[mi][ni], al[mi], bh[ni]);  // lo*hi
                }
        }
        __syncthreads();
    }

    // epilogue -> fp16 (half2 stores)
    #pragma unroll
    for (int mi = 0; mi < 2; mi++) {
        const int row = mBase + wy * 32 + mi * 16 + (lane >> 2);
        #pragma unroll
        for (int ni = 0; ni < 8; ni++) {
            const int col = nBase + wx * 64 + ni * 8 + (lane & 3) * 2;
            *(__half2*)(d_XW1h + (size_t)row * NHID + col) =
                __floats2half2_rn(acc[mi][ni][0], acc[mi][ni][1]);
            *(__half2*)(d_XW1h + (size_t)(row + 8) * NHID + col) =
                __floats2half2_rn(acc[mi][ni][2], acc[mi][ni][3]);
        }
    }
}

// ---------------- FUSED: scan row -> ELL -> H1 row -> HW2 row ----------------
// One block per adj row. LTS traffic: 64KB adj stream + fp16 gather (halved).
__global__ __launch_bounds__(256)
void scan_spmm1_gemm2(const float* __restrict__ adj, const float* __restrict__ b1,
                      const float* __restrict__ W2v) {
    const int row = blockIdx.x;
    const int tid = threadIdx.x;

    __shared__ int   scnt;
    __shared__ int   scol[CAP];
    __shared__ float sval[CAP];
    __shared__ float sh1 [NHID];
    __shared__ float spart[4][NH2];

    if (tid == 0) scnt = 0;
    __syncthreads();

    // ---- scan: build ELL in smem, mirror to global (spmm2 needs it) ----
    const float4* arow = (const float4*)(adj + (size_t)row * NN);
    const int base = row * CAP;
    #pragma unroll 8
    for (int i = tid; i < NN / 4; i += 256) {
        float4 v = arow[i];
        if (v.x != 0.f) { int p = atomicAdd(&scnt, 1); if (p < CAP) { scol[p] = 4*i+0; sval[p] = v.x; d_cols[base+p] = 4*i+0; d_vals[base+p] = v.x; } }
        if (v.y != 0.f) { int p = atomicAdd(&scnt, 1); if (p < CAP) { scol[p] = 4*i+1; sval[p] = v.y; d_cols[base+p] = 4*i+1; d_vals[base+p] = v.y; } }
        if (v.z != 0.f) { int p = atomicAdd(&scnt, 1); if (p < CAP) { scol[p] = 4*i+2; sval[p] = v.z; d_cols[base+p] = 4*i+2; d_vals[base+p] = v.z; } }
        if (v.w != 0.f) { int p = atomicAdd(&scnt, 1); if (p < CAP) { scol[p] = 4*i+3; sval[p] = v.w; d_cols[base+p] = 4*i+3; d_vals[base+p] = v.w; } }
    }
    __syncthreads();
    const int n = min(scnt, CAP);
    if (tid == 0) d_cnt[row] = n;

    // ---- spmm1 (fp16 gather): H1[row][tid] = relu(b1[tid] + sum val*XW1[col][tid]) ----
    float acc = b1[tid];
    int i = 0;
    for (; i + 4 <= n; i += 4) {
        const float v0 = __half2float(d_XW1h[(size_t)scol[i]     * NHID + tid]);
        const float v1 = __half2float(d_XW1h[(size_t)scol[i + 1] * NHID + tid]);
        const float v2 = __half2float(d_XW1h[(size_t)scol[i + 2] * NHID + tid]);
        const float v3 = __half2float(d_XW1h[(size_t)scol[i + 3] * NHID + tid]);
        acc += sval[i] * v0 + sval[i + 1] * v1;
        acc += sval[i + 2] * v2 + sval[i + 3] * v3;
    }
    for (; i < n; i++)
        acc += sval[i] * __half2float(d_XW1h[(size_t)scol[i] * NHID + tid]);
    sh1[tid] = fmaxf(acc, 0.f);
    __syncthreads();

    // ---- gemm2 epilogue: HW2[row][c] = sum_k sh1[k] * W2[k][c] ----
    const int c  = tid & 63;
    const int kq = tid >> 6;             // 0..3
    float s = 0.f;
    #pragma unroll 8
    for (int k = kq * 64; k < kq * 64 + 64; k++)
        s += sh1[k] * W2v[k * NH2 + c];
    spart[kq][c] = s;
    __syncthreads();
    if (tid < NH2)
        d_HW2[(size_t)row * NH2 + tid] =
            (spart[0][tid] + spart[1][tid]) + (spart[2][tid] + spart[3][tid]);
}

// ---------------- SpMM2 + col-max (MLP-4) ----------------
__global__ __launch_bounds__(256)
void spmm2_max(const float* __restrict__ b2) {
    const int r    = threadIdx.x >> 4;     // 0..15
    const int lane = threadIdx.x & 15;     // 0..15
    const int row  = blockIdx.x * 16 + r;

    __shared__ int   soff[16][CAP];
    __shared__ float sval[16][CAP];
    const int n = d_cnt[row];
    for (int i = lane; i < n; i += 16) {
        soff[r][i] = d_cols[row * CAP + i] * NH2;
        sval[r][i] = d_vals[row * CAP + i];
    }
    __syncthreads();

    float4 acc = *(const float4*)(b2 + lane * 4);
    int i = 0;
    for (; i + 4 <= n; i += 4) {
        const float4 v0 = *(const float4*)(d_HW2 + soff[r][i]     + lane * 4);
        const float4 v1 = *(const float4*)(d_HW2 + soff[r][i + 1] + lane * 4);
        const float4 v2 = *(const float4*)(d_HW2 + soff[r][i + 2] + lane * 4);
        const float4 v3 = *(const float4*)(d_HW2 + soff[r][i + 3] + lane * 4);
        const float s0 = sval[r][i], s1 = sval[r][i+1], s2 = sval[r][i+2], s3 = sval[r][i+3];
        acc.x += s0 * v0.x; acc.y += s0 * v0.y; acc.z += s0 * v0.z; acc.w += s0 * v0.w;
        acc.x += s1 * v1.x; acc.y += s1 * v1.y; acc.z += s1 * v1.z; acc.w += s1 * v1.w;
        acc.x += s2 * v2.x; acc.y += s2 * v2.y; acc.z += s2 * v2.z; acc.w += s2 * v2.w;
        acc.x += s3 * v3.x; acc.y += s3 * v3.y; acc.z += s3 * v3.z; acc.w += s3 * v3.w;
    }
    for (; i < n; i++) {
        const float4 v = *(const float4*)(d_HW2 + soff[r][i] + lane * 4);
        const float s = sval[r][i];
        acc.x += s * v.x; acc.y += s * v.y; acc.z += s * v.z; acc.w += s * v.w;
    }
    __syncthreads();
    __shared__ float4 smax[16][16];
    smax[r][lane] = acc;
    __syncthreads();
    if (r == 0) {
        float4 m = smax[0][lane];
        #pragma unroll
        for (int k = 1; k < 16; k++) {
            float4 v = smax[k][lane];
            m.x = fmaxf(m.x, v.x); m.y = fmaxf(m.y, v.y);
            m.z = fmaxf(m.z, v.z); m.w = fmaxf(m.w, v.w);
        }
        atomicMax(&d_gmax[lane * 4 + 0], enc_f(m.x));
        atomicMax(&d_gmax[lane * 4 + 1], enc_f(m.y));
        atomicMax(&d_gmax[lane * 4 + 2], enc_f(m.z));
        atomicMax(&d_gmax[lane * 4 + 3], enc_f(m.w));
    }
}

// ---------------- tiny MLP head: one block ----------------
__global__ void head(const float* __restrict__ W3, const float* __restrict__ b3,
                     const float* __restrict__ W4, const float* __restrict__ b4,
                     const float* __restrict__ W5, const float* __restrict__ b5,
                     float* __restrict__ out) {
    __shared__ float g[NH2], g3[32], g4[16];
    const int t = threadIdx.x;
    g[t] = dec_f(d_gmax[t]);
    __syncthreads();
    if (t < 32) {
        float a = b3[t];
        #pragma unroll
        for (int k = 0; k < NH2; k++) a += g[k] * W3[k * 32 + t];
        g3[t] = fmaxf(a, 0.f);
    }
    __syncthreads();
    if (t < 16) {
        float a = b4[t];
        #pragma unroll
        for (int k = 0; k < 32; k++) a += g3[k] * W4[k * 16 + t];
        g4[t] = fmaxf(a, 0.f);
    }
    __syncthreads();
    if (t < NCLASS) {
        float a = b5[t];
        #pragma unroll
        for (int k = 0; k < 16; k++) a += g4[k] * W5[k * NCLASS + t];
        out[t] = a;
    }
}

// ---------------- launch: ONLY kernel launches, fully graph-capturable ----------------
extern "C" void kernel_launch(void* const* d_in, const int* in_sizes, int n_in,
                              void* d_out, int out_size) {
    const float* x   = (const float*)d_in[0];
    const float* adj = (const float*)d_in[1];
    const float* W1  = (const float*)d_in[2];
    const float* b1  = (const float*)d_in[3];
    const float* W2  = (const float*)d_in[4];
    const float* b2  = (const float*)d_in[5];
    const float* W3  = (const float*)d_in[6];
    const float* b3  = (const float*)d_in[7];
    const float* W4  = (const float*)d_in[8];
    const float* b4  = (const float*)d_in[9];
    const float* W5  = (const float*)d_in[10];
    const float* b5  = (const float*)d_in[11];
    float* out = (float*)d_out;

    init_gmax<<<1, NH2>>>();
    gemm1_tc<<<GEMM1_BLOCKS, 256>>>(x, W1);
    scan_spmm1_gemm2<<<NN, 256>>>(adj, b1, W2);
    spmm2_max<<<NN / 16, 256>>>(b2);
    head<<<1, NH2>>>(W3, b3, W4, b4, W5, b5, out);
}